// round 7
// baseline (speedup 1.0000x reference)
#include <cuda_runtime.h>
#include <math.h>

// Fixed problem shape
#define BB 8
#define NN 32768
#define CC 4
#define MM 11
#define HALO 10

#define THREADS 128
#define KPT 8
#define TILE 256                 // outputs(n) per block
#define NTILES (NN / TILE)       // 128
#define NSAMP (TILE + HALO)      // 266 pair-entries per channel
#define VROW 302                 // per-channel row stride (skewed), float4 / float2 units
#define OROW 308                 // output-bounce row stride (float2), bank-disjoint per channel

typedef unsigned long long u64;
struct uu2 { u64 x, y; };

__device__ __forceinline__ void unpk(u64 v, float& x, float& y) {
    asm("mov.b64 {%0, %1}, %2;" : "=f"(x), "=f"(y) : "l"(v));
}
__device__ __forceinline__ u64 ffma2(u64 a, u64 b, u64 c) {
    u64 d; asm("fma.rn.f32x2 %0, %1, %2, %3;" : "=l"(d) : "l"(a), "l"(b), "l"(c)); return d;
}
__device__ __forceinline__ u64 fmul2(u64 a, u64 b) {
    u64 d; asm("mul.rn.f32x2 %0, %1, %2;" : "=l"(d) : "l"(a), "l"(b)); return d;
}

__device__ __forceinline__ int sk(int e) { return e + (e >> 3); }   // skew

// out[b,c,n] = sum_{j=0..10} z[n-10+j] * P_{c,j}(|z|),  P = w0+w1 a+w2 a^2+w3 a^3+w4 a^4

__global__ __launch_bounds__(THREADS, 6)
void gmp_fir_kernel(const float* __restrict__ x,
                    const float* __restrict__ W,
                    float* __restrict__ out)
{
    __shared__ float4 s_v[CC * VROW];      // entry e: (re_e, re_{e+1}, im_e, im_{e+1})
    __shared__ float2 s_p[CC * OROW];      // a-pairs (VROW scheme); reused as output bounce (OROW)
    __shared__ float2 s_W2[CC * MM * 6];   // duplicated weight pairs, stride 6

    const int tile = blockIdx.x % NTILES;
    const int b    = blockIdx.x / NTILES;
    const int n0   = tile * TILE;

    // Weights: W[c, d*11+j] -> s_W2[(c*11+j)*6 + d] = (w, w)
    for (int i = threadIdx.x; i < CC * 5 * MM; i += THREADS) {
        const int c = i / 55, r = i % 55, d = r / MM, j = r % MM;
        const float w = W[i];
        s_W2[(c * MM + j) * 6 + d] = make_float2(w, w);
    }

    // Stage pair-transposed entries. Entry e uses samples (e, e+1); sample e <-> n = n0-10+e.
    const float4* x4 = (const float4*)x + (size_t)b * NN * 2;
    for (int i = threadIdx.x; i < NSAMP * 2; i += THREADS) {
        const int e  = i >> 1, cp = i & 1;
        const int n  = n0 - HALO + e;
        float4 v0 = make_float4(0.f, 0.f, 0.f, 0.f);
        float4 v1 = make_float4(0.f, 0.f, 0.f, 0.f);
        if (n >= 0)                  v0 = x4[(size_t)n * 2 + cp];
        if (n + 1 >= 0 && n + 1 < NN) v1 = x4[(size_t)(n + 1) * 2 + cp];
        const float a00 = sqrtf(v0.x * v0.x + v0.y * v0.y);   // ch c0, sample e
        const float a01 = sqrtf(v1.x * v1.x + v1.y * v1.y);   // ch c0, sample e+1
        const float a10 = sqrtf(v0.z * v0.z + v0.w * v0.w);   // ch c1, sample e
        const float a11 = sqrtf(v1.z * v1.z + v1.w * v1.w);   // ch c1, sample e+1
        const int c0 = 2 * cp, c1 = c0 + 1;
        s_v[c0 * VROW + sk(e)] = make_float4(v0.x, v1.x, v0.y, v1.y);
        s_v[c1 * VROW + sk(e)] = make_float4(v0.z, v1.z, v0.w, v1.w);
        s_p[c0 * VROW + sk(e)] = make_float2(a00, a01);
        s_p[c1 * VROW + sk(e)] = make_float2(a10, a11);
    }
    __syncthreads();

    // Warp = channel c; lane l owns outputs nl0 = 8l .. 8l+7. Entry offset off -> e = 8l+off.
    const int c = threadIdx.x >> 5;
    const int l = threadIdx.x & 31;
    const int nl0 = 8 * l;
    const int bV = c * VROW + 9 * l;    // sk(8l+off) = 9l + off + (off>>3)
    #define VV(off) (*(const uu2*)&s_v[bV + (off) + ((off) >> 3)])
    #define PV(off) (*(const u64*)&s_p[bV + (off) + ((off) >> 3)])

    const float2* wrow = s_W2 + c * (MM * 6);

    uu2 vv[7];
    u64 pv[7];
    #pragma unroll
    for (int u = 0; u < 6; ++u) { vv[u] = VV(u); pv[u] = PV(u); }

    u64 accR[4], accI[4];
    #pragma unroll
    for (int p = 0; p < 4; ++p) { accR[p] = 0ull; accI[p] = 0ull; }

    #pragma unroll
    for (int j = 0; j < MM; ++j) {
        vv[(j + 6) % 7] = VV(j + 6);
        pv[(j + 6) % 7] = PV(j + 6);

        const uu2 wAB = *(const uu2*)&wrow[j * 6 + 0];   // (W0, W1) duplicated pairs
        const uu2 wCD = *(const uu2*)&wrow[j * 6 + 2];   // (W2, W3)
        const u64 W4  = *(const u64*)&wrow[j * 6 + 4];

        #pragma unroll
        for (int p = 0; p < 4; ++p) {
            const int s = (j + 2 * p) % 7;
            const u64 aa = pv[s];                 // (a_u, a_{u+1})
            const u64 a2 = fmul2(aa, aa);
            u64 t  = ffma2(aa, wAB.y, wAB.x);
            u64 v2 = ffma2(aa, wCD.y, wCD.x);
            v2 = ffma2(a2, W4, v2);
            const u64 P = ffma2(a2, v2, t);       // (p_u, p_{u+1})
            accR[p] = ffma2(vv[s].x, P, accR[p]); // (re_u, re_{u+1})
            accI[p] = ffma2(vv[s].y, P, accI[p]); // (im_u, im_{u+1})
        }
    }

    // Transpose accumulators out through smem (reuse s_p with OROW stride).
    __syncthreads();
    #pragma unroll
    for (int p = 0; p < 4; ++p) {
        float r0, r1, i0, i1;
        unpk(accR[p], r0, r1);
        unpk(accI[p], i0, i1);
        s_p[c * OROW + nl0 + 2 * p]     = make_float2(r0, i0);
        s_p[c * OROW + nl0 + 2 * p + 1] = make_float2(r1, i1);
    }
    __syncthreads();

    float2* o2 = (float2*)out + ((size_t)b * NN + n0) * CC;
    #pragma unroll
    for (int t = 0; t < (TILE * CC) / THREADS; ++t) {
        const int i = threadIdx.x + t * THREADS;
        o2[i] = s_p[(i & 3) * OROW + (i >> 2)];
    }
    #undef VV
    #undef PV
}

extern "C" void kernel_launch(void* const* d_in, const int* in_sizes, int n_in,
                              void* d_out, int out_size)
{
    const float* x = (const float*)d_in[0];   // [B,N,C,2] fp32
    const float* W = (const float*)d_in[1];   // [C, 55]   fp32
    float* out = (float*)d_out;               // [B,N,C,2] fp32
    (void)in_sizes; (void)n_in; (void)out_size;

    gmp_fir_kernel<<<BB * NTILES, THREADS>>>(x, W, out);
}

// round 8
// speedup vs baseline: 1.2371x; 1.2371x over previous
#include <cuda_runtime.h>
#include <math.h>

// Fixed problem shape
#define BB 8
#define NN 32768
#define CC 4
#define MM 11
#define HALO 10

#define THREADS 256
#define KPT 4
#define TILE 256                 // outputs(n) per block
#define NTILES (NN / TILE)       // 128
#define NENT 265                 // pair-entries per channel: e=0..264, samples 0..265
#define VROW 338                 // float4 row stride (skewed max 330); 338%8=2
#define AROW 340                 // float2 row stride; 340%8=4, 2*340%16=8

typedef unsigned long long u64;

__device__ __forceinline__ void unpk(u64 v, float& x, float& y) {
    asm("mov.b64 {%0, %1}, %2;" : "=f"(x), "=f"(y) : "l"(v));
}
__device__ __forceinline__ u64 ffma2(u64 a, u64 b, u64 c) {
    u64 d; asm("fma.rn.f32x2 %0, %1, %2, %3;" : "=l"(d) : "l"(a), "l"(b), "l"(c)); return d;
}
__device__ __forceinline__ u64 fmul2(u64 a, u64 b) {
    u64 d; asm("mul.rn.f32x2 %0, %1, %2;" : "=l"(d) : "l"(a), "l"(b)); return d;
}
__device__ __forceinline__ int sk4(int e) { return e + (e >> 2); }

// out[b,c,n] = sum_{j=0..10} z[n-10+j] * P_{c,j}(|z|),  P = w0+w1 a+w2 a^2+w3 a^3+w4 a^4
// sample s <-> n = n0-10+s; entry e holds samples (e, e+1).
// output nl0+2p(+1), tap j uses entry e = nl0 + j + 2p.

__global__ __launch_bounds__(THREADS, 5)
void gmp_fir_kernel(const float* __restrict__ x,
                    const float* __restrict__ W,
                    float* __restrict__ out)
{
    __shared__ float4 s_v[CC * VROW];      // (re_e, re_{e+1}, im_e, im_{e+1})
    __shared__ float2 s_a[CC * AROW];      // (a_e, a_{e+1})
    __shared__ float2 s_W2[CC * MM * 6];   // duplicated weight pairs, stride 6

    const int tile = blockIdx.x % NTILES;
    const int b    = blockIdx.x / NTILES;
    const int n0   = tile * TILE;

    // Weights: W[c, d*11+j] -> s_W2[(c*11+j)*6 + d] = (w, w)
    for (int i = threadIdx.x; i < CC * 5 * MM; i += THREADS) {
        const int c = i / 55, r = i % 55, d = r / MM, j = r % MM;
        const float w = W[i];
        s_W2[(c * MM + j) * 6 + d] = make_float2(w, w);
    }

    // Stage pair-transposed entries (e, cp): loads samples e and e+1 of channel pair cp.
    const float4* x4 = (const float4*)x + (size_t)b * NN * 2;
    for (int i = threadIdx.x; i < NENT * 2; i += THREADS) {
        const int e  = i >> 1, cp = i & 1;
        const int n  = n0 - HALO + e;
        float4 v0 = make_float4(0.f, 0.f, 0.f, 0.f);
        float4 v1 = make_float4(0.f, 0.f, 0.f, 0.f);
        if (n >= 0)     v0 = x4[(size_t)n * 2 + cp];
        if (n + 1 >= 0) v1 = x4[(size_t)(n + 1) * 2 + cp];
        const int c0 = 2 * cp, c1 = c0 + 1;
        const int se = sk4(e);
        s_v[c0 * VROW + se] = make_float4(v0.x, v1.x, v0.y, v1.y);
        s_v[c1 * VROW + se] = make_float4(v0.z, v1.z, v0.w, v1.w);
        s_a[c0 * AROW + se] = make_float2(sqrtf(v0.x * v0.x + v0.y * v0.y),
                                          sqrtf(v1.x * v1.x + v1.y * v1.y));
        s_a[c1 * AROW + se] = make_float2(sqrtf(v0.z * v0.z + v0.w * v0.w),
                                          sqrtf(v1.z * v1.z + v1.w * v1.w));
    }
    __syncthreads();

    // warp -> channel (2 warps per channel); lane-chunk L = 0..63, outputs nl0 = 4L..4L+3.
    const int wid  = threadIdx.x >> 5;
    const int lane = threadIdx.x & 31;
    const int c    = wid & 3;
    const int L    = ((wid >> 2) << 5) + lane;
    const int nl0  = 4 * L;
    const float4* vbase = s_v + c * VROW + 5 * L;   // sk4(4L+off) = 5L + off + (off>>2)
    const float2* abase = s_a + c * AROW + 5 * L;
    const float2* wrow  = s_W2 + c * (MM * 6);
    #define VV(off) vbase[(off) + ((off) >> 2)]
    #define AV(off) (*(const u64*)&abase[(off) + ((off) >> 2)])

    float4 vv[4];
    u64    av[4];
    #pragma unroll
    for (int u = 0; u < 3; ++u) { vv[u] = VV(u); av[u] = AV(u); }

    u64 accR0 = 0ull, accR1 = 0ull, accI0 = 0ull, accI1 = 0ull;

    #pragma unroll
    for (int j = 0; j < MM; ++j) {
        if (j < MM - 1) {                       // compile-time; last iter needs no new entry
            vv[(j + 3) & 3] = VV(j + 3);
            av[(j + 3) & 3] = AV(j + 3);
        }
        const u64 W0 = *(const u64*)&wrow[j * 6 + 0];
        const u64 W1 = *(const u64*)&wrow[j * 6 + 1];
        const u64 W2 = *(const u64*)&wrow[j * 6 + 2];
        const u64 W3 = *(const u64*)&wrow[j * 6 + 3];
        const u64 W4 = *(const u64*)&wrow[j * 6 + 4];

        {   // pair p=0: entry j -> outputs nl0, nl0+1
            const float4& V = vv[j & 3];
            const u64 aa = av[j & 3];
            const u64 a2 = fmul2(aa, aa);
            u64 t = ffma2(aa, W1, W0);
            u64 q = ffma2(aa, W3, W2);
            q = ffma2(a2, W4, q);
            const u64 P = ffma2(a2, q, t);
            accR0 = ffma2(*(const u64*)&V.x, P, accR0);
            accI0 = ffma2(*(const u64*)&V.z, P, accI0);
        }
        {   // pair p=1: entry j+2 -> outputs nl0+2, nl0+3
            const float4& V = vv[(j + 2) & 3];
            const u64 aa = av[(j + 2) & 3];
            const u64 a2 = fmul2(aa, aa);
            u64 t = ffma2(aa, W1, W0);
            u64 q = ffma2(aa, W3, W2);
            q = ffma2(a2, W4, q);
            const u64 P = ffma2(a2, q, t);
            accR1 = ffma2(*(const u64*)&V.x, P, accR1);
            accI1 = ffma2(*(const u64*)&V.z, P, accI1);
        }
    }
    #undef VV
    #undef AV

    // Unpack and scatter-store (L2 coalesces per 128B line).
    float r0, r1, i0, i1;
    float2* o2 = (float2*)out + ((size_t)b * NN + n0) * CC;
    unpk(accR0, r0, r1); unpk(accI0, i0, i1);
    o2[(nl0 + 0) * CC + c] = make_float2(r0, i0);
    o2[(nl0 + 1) * CC + c] = make_float2(r1, i1);
    unpk(accR1, r0, r1); unpk(accI1, i0, i1);
    o2[(nl0 + 2) * CC + c] = make_float2(r0, i0);
    o2[(nl0 + 3) * CC + c] = make_float2(r1, i1);
}

extern "C" void kernel_launch(void* const* d_in, const int* in_sizes, int n_in,
                              void* d_out, int out_size)
{
    const float* x = (const float*)d_in[0];   // [B,N,C,2] fp32
    const float* W = (const float*)d_in[1];   // [C, 55]   fp32
    float* out = (float*)d_out;               // [B,N,C,2] fp32
    (void)in_sizes; (void)n_in; (void)out_size;

    gmp_fir_kernel<<<BB * NTILES, THREADS>>>(x, W, out);
}

// round 9
// speedup vs baseline: 1.3765x; 1.1127x over previous
#include <cuda_runtime.h>
#include <math.h>

// Fixed problem shape
#define BB 8
#define NN 32768
#define CC 4
#define MM 11
#define HALO 10

#define THREADS 256
#define TILE 256                 // outputs(n) per block
#define NTILES (NN / TILE)       // 128
#define NENT 265                 // pair-entries per channel: e = 0..264 covers samples 0..265
#define VROW 338                 // float4 row stride (skewed max 330)
#define AROW 340                 // float2 row stride; also reused as output bounce (needs >= 1056)

typedef unsigned long long u64;

__device__ __forceinline__ void unpk(u64 v, float& x, float& y) {
    asm("mov.b64 {%0, %1}, %2;" : "=f"(x), "=f"(y) : "l"(v));
}
__device__ __forceinline__ u64 ffma2(u64 a, u64 b, u64 c) {
    u64 d; asm("fma.rn.f32x2 %0, %1, %2, %3;" : "=l"(d) : "l"(a), "l"(b), "l"(c)); return d;
}
__device__ __forceinline__ u64 fmul2(u64 a, u64 b) {
    u64 d; asm("mul.rn.f32x2 %0, %1, %2;" : "=l"(d) : "l"(a), "l"(b)); return d;
}
__device__ __forceinline__ int sk4(int e) { return e + (e >> 2); }

// out[b,c,n] = sum_{j=0..10} z[n-10+j] * P_{c,j}(|z|),  P = w0+w1 a+w2 a^2+w3 a^3+w4 a^4
// sample s <-> n = n0-10+s; entry e holds samples (e, e+1).
// output pair (nl0+2p, nl0+2p+1), tap j uses entry e = nl0 + j + 2p.

__global__ __launch_bounds__(THREADS, 5)
void gmp_fir_kernel(const float* __restrict__ x,
                    const float* __restrict__ W,
                    float* __restrict__ out)
{
    __shared__ float4 s_v[CC * VROW];      // (re_e, re_{e+1}, im_e, im_{e+1})
    __shared__ float2 s_a[CC * AROW];      // (a_e, a_{e+1}); later reused as output bounce
    __shared__ float2 s_W2[CC * MM * 6];   // duplicated weight pairs, stride 6

    const int tile = blockIdx.x % NTILES;
    const int b    = blockIdx.x / NTILES;
    const int n0   = tile * TILE;

    // Weights: W[c, d*11+j] -> s_W2[(c*11+j)*6 + d] = (w, w)
    for (int i = threadIdx.x; i < CC * 5 * MM; i += THREADS) {
        const int c = i / 55, r = i % 55, d = r / MM, j = r % MM;
        const float w = W[i];
        s_W2[(c * MM + j) * 6 + d] = make_float2(w, w);
    }

    // Stage 2 entries per task from 3 sample loads (samples shared between entries).
    // Task (t, cp): entries 2t, 2t+1 of channel pair cp; samples 2t, 2t+1, 2t+2.
    const float4* x4 = (const float4*)x + (size_t)b * NN * 2;
    for (int i = threadIdx.x; i < 266; i += THREADS) {
        const int t = i >> 1, cp = i & 1;
        const int e0 = 2 * t;
        const int n  = n0 - HALO + e0;
        float4 v0 = make_float4(0.f, 0.f, 0.f, 0.f);
        float4 v1 = make_float4(0.f, 0.f, 0.f, 0.f);
        float4 v2 = make_float4(0.f, 0.f, 0.f, 0.f);
        if (n >= 0)     v0 = x4[(size_t)n * 2 + cp];
        if (n + 1 >= 0) v1 = x4[(size_t)(n + 1) * 2 + cp];
        const bool has2 = (t <= 131);                  // entry e0+1 exists (e0+1 <= 264)
        if (has2 && n + 2 >= 0) v2 = x4[(size_t)(n + 2) * 2 + cp];

        const float a0x = sqrtf(v0.x * v0.x + v0.y * v0.y);
        const float a0z = sqrtf(v0.z * v0.z + v0.w * v0.w);
        const float a1x = sqrtf(v1.x * v1.x + v1.y * v1.y);
        const float a1z = sqrtf(v1.z * v1.z + v1.w * v1.w);
        const int c0 = 2 * cp, c1 = c0 + 1;
        const int s0 = sk4(e0);
        s_v[c0 * VROW + s0] = make_float4(v0.x, v1.x, v0.y, v1.y);
        s_v[c1 * VROW + s0] = make_float4(v0.z, v1.z, v0.w, v1.w);
        s_a[c0 * AROW + s0] = make_float2(a0x, a1x);
        s_a[c1 * AROW + s0] = make_float2(a0z, a1z);
        if (has2) {
            const float a2x = sqrtf(v2.x * v2.x + v2.y * v2.y);
            const float a2z = sqrtf(v2.z * v2.z + v2.w * v2.w);
            const int s1 = sk4(e0 + 1);
            s_v[c0 * VROW + s1] = make_float4(v1.x, v2.x, v1.y, v2.y);
            s_v[c1 * VROW + s1] = make_float4(v1.z, v2.z, v1.w, v2.w);
            s_a[c0 * AROW + s1] = make_float2(a1x, a2x);
            s_a[c1 * AROW + s1] = make_float2(a1z, a2z);
        }
    }
    __syncthreads();

    // warp -> channel (2 warps per channel); lane-chunk L = 0..63, outputs nl0 = 4L..4L+3.
    const int wid  = threadIdx.x >> 5;
    const int lane = threadIdx.x & 31;
    const int c    = wid & 3;
    const int L    = ((wid >> 2) << 5) + lane;
    const int nl0  = 4 * L;
    const float4* vbase = s_v + c * VROW + 5 * L;   // sk4(4L+off) = 5L + off + (off>>2)
    const float2* abase = s_a + c * AROW + 5 * L;
    const float2* wrow  = s_W2 + c * (MM * 6);
    #define VV(off) vbase[(off) + ((off) >> 2)]
    #define AV(off) (*(const u64*)&abase[(off) + ((off) >> 2)])

    float4 vv[4];
    u64    av[4];
    #pragma unroll
    for (int u = 0; u < 3; ++u) { vv[u] = VV(u); av[u] = AV(u); }

    u64 accR0 = 0ull, accR1 = 0ull, accI0 = 0ull, accI1 = 0ull;

    #pragma unroll
    for (int j = 0; j < MM; ++j) {
        if (j < MM - 1) {
            vv[(j + 3) & 3] = VV(j + 3);
            av[(j + 3) & 3] = AV(j + 3);
        }
        const u64 W0 = *(const u64*)&wrow[j * 6 + 0];
        const u64 W1 = *(const u64*)&wrow[j * 6 + 1];
        const u64 W2 = *(const u64*)&wrow[j * 6 + 2];
        const u64 W3 = *(const u64*)&wrow[j * 6 + 3];
        const u64 W4 = *(const u64*)&wrow[j * 6 + 4];

        {   // pair p=0: entry j -> outputs nl0, nl0+1
            const float4& V = vv[j & 3];
            const u64 aa = av[j & 3];
            const u64 a2 = fmul2(aa, aa);
            u64 t = ffma2(aa, W1, W0);
            u64 q = ffma2(aa, W3, W2);
            q = ffma2(a2, W4, q);
            const u64 P = ffma2(a2, q, t);
            accR0 = ffma2(*(const u64*)&V.x, P, accR0);
            accI0 = ffma2(*(const u64*)&V.z, P, accI0);
        }
        {   // pair p=1: entry j+2 -> outputs nl0+2, nl0+3
            const float4& V = vv[(j + 2) & 3];
            const u64 aa = av[(j + 2) & 3];
            const u64 a2 = fmul2(aa, aa);
            u64 t = ffma2(aa, W1, W0);
            u64 q = ffma2(aa, W3, W2);
            q = ffma2(a2, W4, q);
            const u64 P = ffma2(a2, q, t);
            accR1 = ffma2(*(const u64*)&V.x, P, accR1);
            accI1 = ffma2(*(const u64*)&V.z, P, accI1);
        }
    }
    #undef VV
    #undef AV

    // Bounce through smem (reuse s_a) for coalesced global stores.
    __syncthreads();                      // all s_a reads done before overwrite
    {
        float r0, r1, i0, i1;
        unpk(accR0, r0, r1); unpk(accI0, i0, i1);
        int e;
        e = (nl0 + 0) * CC + c; s_a[e + (e >> 5)] = make_float2(r0, i0);
        e = (nl0 + 1) * CC + c; s_a[e + (e >> 5)] = make_float2(r1, i1);
        unpk(accR1, r0, r1); unpk(accI1, i0, i1);
        e = (nl0 + 2) * CC + c; s_a[e + (e >> 5)] = make_float2(r0, i0);
        e = (nl0 + 3) * CC + c; s_a[e + (e >> 5)] = make_float2(r1, i1);
    }
    __syncthreads();

    float2* o2 = (float2*)out + ((size_t)b * NN + n0) * CC;
    #pragma unroll
    for (int t = 0; t < (TILE * CC) / THREADS; ++t) {
        const int i = threadIdx.x + t * THREADS;
        o2[i] = s_a[i + (i >> 5)];
    }
}

extern "C" void kernel_launch(void* const* d_in, const int* in_sizes, int n_in,
                              void* d_out, int out_size)
{
    const float* x = (const float*)d_in[0];   // [B,N,C,2] fp32
    const float* W = (const float*)d_in[1];   // [C, 55]   fp32
    float* out = (float*)d_out;               // [B,N,C,2] fp32
    (void)in_sizes; (void)n_in; (void)out_size;

    gmp_fir_kernel<<<BB * NTILES, THREADS>>>(x, W, out);
}